// round 1
// baseline (speedup 1.0000x reference)
#include <cuda_runtime.h>
#include <cuda_bf16.h>
#include <float.h>

// GaussianInfoNCELoss: loss = mean_i [ logsumexp_j t(i,j) - t(i,i) ]
//   t(i,j) = dot(x_i, y_j) - 0.5*|y_j|^2      (row-constant -0.5|x_i|^2 cancels)
// x = features_nc reshaped (K, D), y = features_c reshaped (K, D), K=8192, D=128.

#define D 128
#define BM 64
#define TN 64
#define XPAD 4                  // row stride BM+XPAD = 68 floats (16B-aligned rows)
#define ROWSTRIDE (BM + XPAD)

__device__ float g_ysq[16384];      // 0.5*|y_j|^2
__device__ float g_partial[512];    // per-block loss partial sums

// ---------------------------------------------------------------------------
// Kernel 1: ysq[j] = 0.5 * sum_d y[j][d]^2   (warp per row)
// ---------------------------------------------------------------------------
__global__ void ysq_kernel(const float* __restrict__ Y, int K) {
    int w    = (blockIdx.x * blockDim.x + threadIdx.x) >> 5;
    int lane = threadIdx.x & 31;
    if (w >= K) return;
    const float* yr = Y + (size_t)w * D;
    float a = 0.f;
    #pragma unroll
    for (int d = lane; d < D; d += 32) {
        float v = yr[d];
        a = fmaf(v, v, a);
    }
    #pragma unroll
    for (int off = 16; off; off >>= 1)
        a += __shfl_xor_sync(0xffffffffu, a, off);
    if (lane == 0) g_ysq[w] = 0.5f * a;
}

// ---------------------------------------------------------------------------
// Kernel 2: fused GEMM + online logsumexp.
// Block: 256 threads as 16x16 (ty=row group, tx=col group), each thread 4x4.
// X tile (BM x D) persistent in smem (transposed: [d][r]); Y tiles streamed.
// ---------------------------------------------------------------------------
__global__ __launch_bounds__(256, 1)
void infonce_kernel(const float* __restrict__ X, const float* __restrict__ Y,
                    int K) {
    extern __shared__ float smem[];
    float* Xs = smem;                        // [D][ROWSTRIDE]
    float* Ys = smem + D * ROWSTRIDE;        // [D][ROWSTRIDE]
    __shared__ float ysq_s[TN];
    __shared__ float red[16];

    const int tid = threadIdx.x;
    const int ty  = tid >> 4;       // 0..15 row group
    const int tx  = tid & 15;       // 0..15 col group
    const int row0 = blockIdx.x * BM;

    // Load X tile, transposed into smem: Xs[d][r]
    #pragma unroll 4
    for (int idx = tid; idx < BM * D; idx += 256) {
        int r = idx >> 7;           // 0..63
        int d = idx & (D - 1);      // coalesced on gmem
        Xs[d * ROWSTRIDE + r] = X[(row0 + r) * D + d];
    }

    float m[4], s[4], dg[4];
    #pragma unroll
    for (int i = 0; i < 4; i++) { m[i] = -FLT_MAX; s[i] = 0.f; dg[i] = 0.f; }

    for (int jt = 0; jt < K; jt += TN) {
        __syncthreads();   // previous tile fully consumed (also orders Xs load)
        // Load Y tile transposed: Ys[d][c]
        #pragma unroll 4
        for (int idx = tid; idx < TN * D; idx += 256) {
            int c = idx >> 7;
            int d = idx & (D - 1);
            Ys[d * ROWSTRIDE + c] = Y[(jt + c) * D + d];
        }
        if (tid < TN) ysq_s[tid] = g_ysq[jt + tid];
        __syncthreads();

        float acc[4][4];
        #pragma unroll
        for (int i = 0; i < 4; i++)
            #pragma unroll
            for (int j = 0; j < 4; j++) acc[i][j] = 0.f;

        #pragma unroll 8
        for (int d = 0; d < D; d++) {
            float4 xv = *reinterpret_cast<const float4*>(Xs + d * ROWSTRIDE + 4 * ty);
            float4 yv = *reinterpret_cast<const float4*>(Ys + d * ROWSTRIDE + 4 * tx);
            float xa[4] = {xv.x, xv.y, xv.z, xv.w};
            float ya[4] = {yv.x, yv.y, yv.z, yv.w};
            #pragma unroll
            for (int i = 0; i < 4; i++)
                #pragma unroll
                for (int j = 0; j < 4; j++)
                    acc[i][j] = fmaf(xa[i], ya[j], acc[i][j]);
        }

        // t = dot - 0.5|y|^2
        float yq[4];
        #pragma unroll
        for (int j = 0; j < 4; j++) yq[j] = ysq_s[4 * tx + j];

        float tval[4][4];
        #pragma unroll
        for (int i = 0; i < 4; i++)
            #pragma unroll
            for (int j = 0; j < 4; j++) tval[i][j] = acc[i][j] - yq[j];

        // diagonal: only tile jt==row0 holds it, at ty==tx, i==j
        if (jt == row0 && tx == ty) {
            #pragma unroll
            for (int i = 0; i < 4; i++) dg[i] += tval[i][i];
        }

        // online logsumexp per row (reduce across the 16 tx lanes of a row)
        #pragma unroll
        for (int i = 0; i < 4; i++) {
            float mt = fmaxf(fmaxf(tval[i][0], tval[i][1]),
                             fmaxf(tval[i][2], tval[i][3]));
            #pragma unroll
            for (int off = 8; off; off >>= 1)
                mt = fmaxf(mt, __shfl_xor_sync(0xffffffffu, mt, off));
            float mnew = fmaxf(m[i], mt);
            float st = __expf(tval[i][0] - mnew) + __expf(tval[i][1] - mnew)
                     + __expf(tval[i][2] - mnew) + __expf(tval[i][3] - mnew);
            #pragma unroll
            for (int off = 8; off; off >>= 1)
                st += __shfl_xor_sync(0xffffffffu, st, off);
            s[i] = s[i] * __expf(m[i] - mnew) + st;
            m[i] = mnew;
        }
    }

    // gather diag across the row group (only one lane holds nonzero)
    #pragma unroll
    for (int i = 0; i < 4; i++) {
        #pragma unroll
        for (int off = 8; off; off >>= 1)
            dg[i] += __shfl_xor_sync(0xffffffffu, dg[i], off);
    }

    // per-row loss = m + log(s) - diag ; sum over this thread's 4 rows (tx==0)
    float part = 0.f;
    if (tx == 0) {
        #pragma unroll
        for (int i = 0; i < 4; i++)
            part += m[i] + __logf(s[i]) - dg[i];
        red[ty] = part;
    }
    __syncthreads();
    if (tid == 0) {
        float tot = 0.f;
        #pragma unroll
        for (int k = 0; k < 16; k++) tot += red[k];
        g_partial[blockIdx.x] = tot;
    }
}

// ---------------------------------------------------------------------------
// Kernel 3: reduce partials -> scalar mean
// ---------------------------------------------------------------------------
__global__ void finalize_kernel(float* __restrict__ out, int nblk, float invK) {
    __shared__ float sm[4];
    int tid = threadIdx.x;       // 128 threads
    float v = 0.f;
    for (int i = tid; i < nblk; i += 128) v += g_partial[i];
    #pragma unroll
    for (int off = 16; off; off >>= 1)
        v += __shfl_xor_sync(0xffffffffu, v, off);
    if ((tid & 31) == 0) sm[tid >> 5] = v;
    __syncthreads();
    if (tid == 0)
        out[0] = (sm[0] + sm[1] + sm[2] + sm[3]) * invK;
}

// ---------------------------------------------------------------------------
extern "C" void kernel_launch(void* const* d_in, const int* in_sizes, int n_in,
                              void* d_out, int out_size) {
    const float* X = (const float*)d_in[0];   // features_nc
    const float* Y = (const float*)d_in[1];   // features_c
    int K = in_sizes[0] / D;                  // 8192

    size_t smem_bytes = (size_t)2 * D * ROWSTRIDE * sizeof(float);  // ~68 KB
    cudaFuncSetAttribute(infonce_kernel,
                         cudaFuncAttributeMaxDynamicSharedMemorySize,
                         (int)smem_bytes);

    int nblk = K / BM;                        // 128
    ysq_kernel<<<(K + 7) / 8, 256>>>(Y, K);
    infonce_kernel<<<nblk, 256, smem_bytes>>>(X, Y, K);
    finalize_kernel<<<1, 128>>>((float*)d_out, nblk, 1.0f / (float)K);
}

// round 3
// speedup vs baseline: 8.6184x; 8.6184x over previous
#include <cuda_runtime.h>
#include <cuda_bf16.h>
#include <float.h>
#include <stdint.h>

// loss = mean_i [ logsumexp_j t(i,j) - t(i,i) ],  t(i,j) = x_i.y_j - 0.5|y_j|^2
// K=8192, D=128. bf16 mma.sync (baseline PTX) + fused online logsumexp.

#define DD     128
#define KTOT   8192
#define CSPLIT 2
#define COLS   (KTOT / CSPLIT)     // 4096 per CTA
#define BM     128                 // rows per CTA
#define TN     128                 // col tile
#define NT     (COLS / TN)         // 32 tiles
#define YSTRIDE 272                // bytes per smem row (128 bf16 + 8 pad)

__device__ __nv_bfloat16 g_xb[KTOT * DD];
__device__ __nv_bfloat16 g_yb[KTOT * DD];
__device__ float g_ysq[KTOT];
__device__ float g_diag[KTOT];
__device__ float g_m[CSPLIT * KTOT];
__device__ float g_s[CSPLIT * KTOT];

// ---------------------------------------------------------------------------
__device__ __forceinline__ uint32_t s2u(const void* p) {
    uint32_t a;
    asm("{ .reg .u64 t; cvta.to.shared.u64 t, %1; cvt.u32.u64 %0, t; }"
        : "=r"(a) : "l"(p));
    return a;
}
__device__ __forceinline__ void cp16(uint32_t dst, const void* src) {
    asm volatile("cp.async.cg.shared.global [%0], [%1], 16;"
                 :: "r"(dst), "l"(src) : "memory");
}
__device__ __forceinline__ void ldsm4(uint32_t& r0, uint32_t& r1,
                                      uint32_t& r2, uint32_t& r3, uint32_t a) {
    asm volatile("ldmatrix.sync.aligned.m8n8.x4.shared.b16 {%0,%1,%2,%3}, [%4];"
                 : "=r"(r0), "=r"(r1), "=r"(r2), "=r"(r3) : "r"(a));
}
__device__ __forceinline__ void mma16816(float* d, const uint32_t* a,
                                         uint32_t b0, uint32_t b1) {
    asm volatile(
        "mma.sync.aligned.m16n8k16.row.col.f32.bf16.bf16.f32 "
        "{%0,%1,%2,%3}, {%4,%5,%6,%7}, {%8,%9}, {%0,%1,%2,%3};"
        : "+f"(d[0]), "+f"(d[1]), "+f"(d[2]), "+f"(d[3])
        : "r"(a[0]), "r"(a[1]), "r"(a[2]), "r"(a[3]), "r"(b0), "r"(b1));
}

// ---------------------------------------------------------------------------
// Prep: bf16 conversion + 0.5|y|^2 + exact fp32 diagonal. One warp per row.
// ---------------------------------------------------------------------------
__global__ void prep_kernel(const float* __restrict__ X, const float* __restrict__ Y) {
    int gw   = (blockIdx.x * blockDim.x + threadIdx.x) >> 5;
    int lane = threadIdx.x & 31;
    if (gw >= KTOT) return;
    float4 xv = ((const float4*)(X + (size_t)gw * DD))[lane];
    float4 yv = ((const float4*)(Y + (size_t)gw * DD))[lane];
    float dot = xv.x * yv.x + xv.y * yv.y + xv.z * yv.z + xv.w * yv.w;
    float ysq = yv.x * yv.x + yv.y * yv.y + yv.z * yv.z + yv.w * yv.w;
    #pragma unroll
    for (int off = 16; off; off >>= 1) {
        dot += __shfl_xor_sync(0xffffffffu, dot, off);
        ysq += __shfl_xor_sync(0xffffffffu, ysq, off);
    }
    __nv_bfloat162 x01 = __floats2bfloat162_rn(xv.x, xv.y);
    __nv_bfloat162 x23 = __floats2bfloat162_rn(xv.z, xv.w);
    __nv_bfloat162 y01 = __floats2bfloat162_rn(yv.x, yv.y);
    __nv_bfloat162 y23 = __floats2bfloat162_rn(yv.z, yv.w);
    uint2 xp, yp;
    xp.x = *(const unsigned*)&x01;  xp.y = *(const unsigned*)&x23;
    yp.x = *(const unsigned*)&y01;  yp.y = *(const unsigned*)&y23;
    ((uint2*)(g_xb + (size_t)gw * DD))[lane] = xp;
    ((uint2*)(g_yb + (size_t)gw * DD))[lane] = yp;
    if (lane == 0) {
        g_ysq[gw]  = 0.5f * ysq;
        g_diag[gw] = dot - 0.5f * ysq;
    }
}

// ---------------------------------------------------------------------------
// Main: bf16 HMMA GEMM + fused online logsumexp.
// 256 threads = 8 warps in 4(m) x 2(n); warp tile 32x64; thread 4 rows x 16 cols.
// ---------------------------------------------------------------------------
__global__ __launch_bounds__(256)
void infonce_mma_kernel() {
    extern __shared__ char dsm[];
    __shared__ float mh[2][BM], sh[2][BM];

    const int tid  = threadIdx.x;
    const int wid  = tid >> 5;
    const int lane = tid & 31;
    const int half = blockIdx.x & 1;
    const int row0 = (blockIdx.x >> 1) * BM;
    const int col0 = half * COLS;

    const uint32_t base = s2u(dsm);
    const uint32_t xs   = base;                      // 128*272 = 34816
    const uint32_t ysb[2] = {base + 34816u, base + 69632u};
    const uint32_t yqb[2] = {base + 104448u, base + 104960u};

    // ---- X tile load (once) ----
    {
        const __nv_bfloat16* xg = g_xb + (size_t)row0 * DD;
        #pragma unroll
        for (int i = 0; i < 8; i++) {
            int c = i * 256 + tid;
            int r = c >> 4, kc = c & 15;
            cp16(xs + r * YSTRIDE + kc * 16, xg + r * DD + kc * 8);
        }
        asm volatile("cp.async.commit_group;" ::: "memory");
        asm volatile("cp.async.wait_group 0;" ::: "memory");
    }
    __syncthreads();

    // ---- A fragments for this warp's 32 rows, all K, held in registers ----
    const int mo = (wid >> 1) * 32;
    const int no = (wid & 1) * 64;
    uint32_t afrag[2][8][4];
    {
        uint32_t arow = (uint32_t)(mo + (lane & 15));
        uint32_t acol = (uint32_t)(lane >> 4) * 16u;
        #pragma unroll
        for (int mt = 0; mt < 2; mt++)
            #pragma unroll
            for (int kt = 0; kt < 8; kt++)
                ldsm4(afrag[mt][kt][0], afrag[mt][kt][1],
                      afrag[mt][kt][2], afrag[mt][kt][3],
                      xs + (arow + mt * 16u) * YSTRIDE + kt * 32u + acol);
    }

    // lane-dependent B address parts
    const uint32_t brow = (uint32_t)(no + ((lane >> 4) & 1) * 8 + (lane & 7));
    const uint32_t bkof = (uint32_t)((lane >> 3) & 1) * 16u;
    const int tg = lane & 3;

    float m_run[4], s_run[4];
    #pragma unroll
    for (int i = 0; i < 4; i++) { m_run[i] = -FLT_MAX; s_run[i] = 0.f; }

    // ---- prologue: load Y tile 0 ----
    {
        const __nv_bfloat16* yg = g_yb + (size_t)col0 * DD;
        #pragma unroll
        for (int i = 0; i < 8; i++) {
            int c = i * 256 + tid;
            int r = c >> 4, kc = c & 15;
            cp16(ysb[0] + r * YSTRIDE + kc * 16, yg + r * DD + kc * 8);
        }
        if (tid < 32) cp16(yqb[0] + tid * 16, g_ysq + col0 + tid * 4);
        asm volatile("cp.async.commit_group;" ::: "memory");
    }

    #pragma unroll 1
    for (int t = 0; t < NT; t++) {
        if (t + 1 < NT) {
            const int nb = (t + 1) & 1;
            const __nv_bfloat16* yg = g_yb + (size_t)(col0 + (t + 1) * TN) * DD;
            #pragma unroll
            for (int i = 0; i < 8; i++) {
                int c = i * 256 + tid;
                int r = c >> 4, kc = c & 15;
                cp16(ysb[nb] + r * YSTRIDE + kc * 16, yg + r * DD + kc * 8);
            }
            if (tid < 32) cp16(yqb[nb] + tid * 16, g_ysq + col0 + (t + 1) * TN + tid * 4);
            asm volatile("cp.async.commit_group;" ::: "memory");
            asm volatile("cp.async.wait_group 1;" ::: "memory");
        } else {
            asm volatile("cp.async.wait_group 0;" ::: "memory");
        }
        __syncthreads();

        const int cb = t & 1;
        const uint32_t yb = ysb[cb];

        float acc[2][8][4];
        #pragma unroll
        for (int mt = 0; mt < 2; mt++)
            #pragma unroll
            for (int nt = 0; nt < 8; nt++)
                #pragma unroll
                for (int q = 0; q < 4; q++) acc[mt][nt][q] = 0.f;

        #pragma unroll
        for (int kt = 0; kt < 8; kt++) {
            #pragma unroll
            for (int np = 0; np < 4; np++) {
                uint32_t b0, b1, b2, b3;
                ldsm4(b0, b1, b2, b3,
                      yb + (brow + np * 16u) * YSTRIDE + kt * 32u + bkof);
                mma16816(acc[0][2 * np],     afrag[0][kt], b0, b1);
                mma16816(acc[1][2 * np],     afrag[1][kt], b0, b1);
                mma16816(acc[0][2 * np + 1], afrag[0][kt], b2, b3);
                mma16816(acc[1][2 * np + 1], afrag[1][kt], b2, b3);
            }
        }

        // ---- epilogue: online logsumexp over this tile's 64 cols/warp ----
        const float* ysqp = (const float*)(dsm + 104448 + cb * 512);
        float2 yq[8];
        #pragma unroll
        for (int nt = 0; nt < 8; nt++)
            yq[nt] = *(const float2*)(ysqp + no + nt * 8 + 2 * tg);

        #pragma unroll
        for (int ri = 0; ri < 4; ri++) {
            const int mt = ri >> 1, hi = ri & 1;
            float vmax = -FLT_MAX;
            #pragma unroll
            for (int nt = 0; nt < 8; nt++) {
                float v0 = acc[mt][nt][2 * hi]     - yq[nt].x;
                float v1 = acc[mt][nt][2 * hi + 1] - yq[nt].y;
                vmax = fmaxf(vmax, fmaxf(v0, v1));
            }
            vmax = fmaxf(vmax, __shfl_xor_sync(0xffffffffu, vmax, 1));
            vmax = fmaxf(vmax, __shfl_xor_sync(0xffffffffu, vmax, 2));
            float mn = fmaxf(m_run[ri], vmax);
            float cs = 0.f;
            #pragma unroll
            for (int nt = 0; nt < 8; nt++) {
                cs += __expf(acc[mt][nt][2 * hi]     - yq[nt].x - mn);
                cs += __expf(acc[mt][nt][2 * hi + 1] - yq[nt].y - mn);
            }
            cs += __shfl_xor_sync(0xffffffffu, cs, 1);
            cs += __shfl_xor_sync(0xffffffffu, cs, 2);
            s_run[ri] = fmaf(s_run[ri], __expf(m_run[ri] - mn), cs);
            m_run[ri] = mn;
        }
    }

    // ---- merge the two n-group halves within the CTA ----
    if ((lane & 3) == 0) {
        const int g  = lane >> 2;
        const int ng = wid & 1;
        #pragma unroll
        for (int ri = 0; ri < 4; ri++) {
            int rowl = mo + g + (ri & 1) * 8 + (ri >> 1) * 16;
            mh[ng][rowl] = m_run[ri];
            sh[ng][rowl] = s_run[ri];
        }
    }
    __syncthreads();
    if (tid < BM) {
        float m0 = mh[0][tid], m1 = mh[1][tid];
        float s0 = sh[0][tid], s1 = sh[1][tid];
        float M = fmaxf(m0, m1);
        float S = fmaf(s0, __expf(m0 - M), s1 * __expf(m1 - M));
        g_m[half * KTOT + row0 + tid] = M;
        g_s[half * KTOT + row0 + tid] = S;
    }
}

// ---------------------------------------------------------------------------
// Finalize: merge column halves per row, subtract exact diagonal, mean.
// ---------------------------------------------------------------------------
__global__ void finalize_kernel(float* __restrict__ out) {
    __shared__ float red[32];
    int tid = threadIdx.x;  // 1024
    float acc = 0.f;
    for (int i = tid; i < KTOT; i += 1024) {
        float m0 = g_m[i],        s0 = g_s[i];
        float m1 = g_m[KTOT + i], s1 = g_s[KTOT + i];
        float M  = fmaxf(m0, m1);
        float lse = M + __logf(fmaf(s0, __expf(m0 - M), s1 * __expf(m1 - M)));
        acc += lse - g_diag[i];
    }
    #pragma unroll
    for (int off = 16; off; off >>= 1)
        acc += __shfl_xor_sync(0xffffffffu, acc, off);
    if ((tid & 31) == 0) red[tid >> 5] = acc;
    __syncthreads();
    if (tid < 32) {
        float v = red[tid];
        #pragma unroll
        for (int off = 16; off; off >>= 1)
            v += __shfl_xor_sync(0xffffffffu, v, off);
        if (tid == 0) out[0] = v * (1.0f / (float)KTOT);
    }
}

// ---------------------------------------------------------------------------
extern "C" void kernel_launch(void* const* d_in, const int* in_sizes, int n_in,
                              void* d_out, int out_size) {
    const float* X = (const float*)d_in[0];  // features_nc
    const float* Y = (const float*)d_in[1];  // features_c

    const size_t dsmem = 104448 + 1024;  // X + 2*Y + 2*ysq = 105472 B
    cudaFuncSetAttribute(infonce_mma_kernel,
                         cudaFuncAttributeMaxDynamicSharedMemorySize, (int)dsmem);

    prep_kernel<<<(KTOT * 32) / 256, 256>>>(X, Y);
    infonce_mma_kernel<<<(KTOT / BM) * CSPLIT, 256, dsmem>>>();
    finalize_kernel<<<1, 1024>>>((float*)d_out);
}

// round 4
// speedup vs baseline: 10.0860x; 1.1703x over previous
#include <cuda_runtime.h>
#include <cuda_fp16.h>
#include <float.h>
#include <stdint.h>

// loss = mean_i [ logsumexp_j t(i,j) - t(i,i) ],  t(i,j) = x_i.y_j - 0.5|y_j|^2
// K=8192, D=128. f16 mma.sync (f16 accum, 2x rate) in log2 domain, persistent
// 148-CTA grid, fused online logsumexp. Diagonal exact in fp32.

#define DD      128
#define KTOT    8192
#define BM      128
#define TN      128
#define YSTRIDE 272                // bytes per smem row (128 f16 + 8 pad)
#define NUNITS  1024               // (8192/128 rb) * (8192/512 cc)
#define NCTA    148
#define LOG2E   1.4426950408889634f
#define LN2     0.6931471805599453f

__device__ __half g_xb[KTOT * DD];      // x * log2e, f16
__device__ __half g_yb[KTOT * DD];      // y, f16
__device__ float  g_ysq[KTOT];          // 0.5*log2e*|y|^2
__device__ float  g_diag[KTOT];         // exact t(i,i), natural units
__device__ float  g_m[NUNITS * BM];     // per-unit row max (log2 domain)
__device__ float  g_s[NUNITS * BM];     // per-unit row sum of 2^(t'-m)
__device__ float  g_partial[32];

// ---------------------------------------------------------------------------
__device__ __forceinline__ uint32_t s2u(const void* p) {
    uint32_t a;
    asm("{ .reg .u64 t; cvta.to.shared.u64 t, %1; cvt.u32.u64 %0, t; }"
        : "=r"(a) : "l"(p));
    return a;
}
__device__ __forceinline__ void cp16(uint32_t dst, const void* src) {
    asm volatile("cp.async.cg.shared.global [%0], [%1], 16;"
                 :: "r"(dst), "l"(src) : "memory");
}
__device__ __forceinline__ void ldsm4(uint32_t& r0, uint32_t& r1,
                                      uint32_t& r2, uint32_t& r3, uint32_t a) {
    asm volatile("ldmatrix.sync.aligned.m8n8.x4.shared.b16 {%0,%1,%2,%3}, [%4];"
                 : "=r"(r0), "=r"(r1), "=r"(r2), "=r"(r3) : "r"(a));
}
__device__ __forceinline__ void mma_h(uint32_t* d, const uint32_t* a,
                                      uint32_t b0, uint32_t b1) {
    asm volatile(
        "mma.sync.aligned.m16n8k16.row.col.f16.f16.f16.f16 "
        "{%0,%1}, {%2,%3,%4,%5}, {%6,%7}, {%0,%1};"
        : "+r"(d[0]), "+r"(d[1])
        : "r"(a[0]), "r"(a[1]), "r"(a[2]), "r"(a[3]), "r"(b0), "r"(b1));
}
__device__ __forceinline__ float ex2(float x) {
    float r;
    asm("ex2.approx.ftz.f32 %0, %1;" : "=f"(r) : "f"(x));
    return r;
}
__device__ __forceinline__ float lg2(float x) {
    float r;
    asm("lg2.approx.ftz.f32 %0, %1;" : "=f"(r) : "f"(x));
    return r;
}

// ---------------------------------------------------------------------------
// Prep: f16 conversion (+log2e scale on X), scaled ysq, exact fp32 diagonal.
// ---------------------------------------------------------------------------
__global__ void prep_kernel(const float* __restrict__ X, const float* __restrict__ Y) {
    int gw   = (blockIdx.x * blockDim.x + threadIdx.x) >> 5;
    int lane = threadIdx.x & 31;
    if (gw >= KTOT) return;
    float4 xv = ((const float4*)(X + (size_t)gw * DD))[lane];
    float4 yv = ((const float4*)(Y + (size_t)gw * DD))[lane];
    float dot = xv.x * yv.x + xv.y * yv.y + xv.z * yv.z + xv.w * yv.w;
    float ysq = yv.x * yv.x + yv.y * yv.y + yv.z * yv.z + yv.w * yv.w;
    #pragma unroll
    for (int off = 16; off; off >>= 1) {
        dot += __shfl_xor_sync(0xffffffffu, dot, off);
        ysq += __shfl_xor_sync(0xffffffffu, ysq, off);
    }
    __half2 x01 = __float22half2_rn(make_float2(xv.x * LOG2E, xv.y * LOG2E));
    __half2 x23 = __float22half2_rn(make_float2(xv.z * LOG2E, xv.w * LOG2E));
    __half2 y01 = __float22half2_rn(make_float2(yv.x, yv.y));
    __half2 y23 = __float22half2_rn(make_float2(yv.z, yv.w));
    uint2 xp, yp;
    xp.x = *(const unsigned*)&x01;  xp.y = *(const unsigned*)&x23;
    yp.x = *(const unsigned*)&y01;  yp.y = *(const unsigned*)&y23;
    ((uint2*)(g_xb + (size_t)gw * DD))[lane] = xp;
    ((uint2*)(g_yb + (size_t)gw * DD))[lane] = yp;
    if (lane == 0) {
        g_ysq[gw]  = 0.5f * LOG2E * ysq;
        g_diag[gw] = dot - 0.5f * ysq;
    }
}

// ---------------------------------------------------------------------------
// Main: persistent CTAs, f16 HMMA + fused online logsumexp (log2 domain).
// 256 threads = 8 warps in 4(m) x 2(n); warp tile 32x64.
// Global tile index g in [0,4096): rb = g>>6, col = (g&63)*128, unit = g>>2.
// ---------------------------------------------------------------------------
__global__ __launch_bounds__(256)
void infonce_mma_kernel() {
    extern __shared__ char dsm[];
    __shared__ float mh[2][BM], sh[2][BM];

    const int tid  = threadIdx.x;
    const int wid  = tid >> 5;
    const int lane = tid & 31;

    const uint32_t base = s2u(dsm);
    const uint32_t xsb[2] = {base, base + 34816u};
    const uint32_t ysb[2] = {base + 69632u, base + 104448u};
    const uint32_t yqb[2] = {base + 139264u, base + 139776u};

    const int u0 = (blockIdx.x * NUNITS) / NCTA;
    const int u1 = ((blockIdx.x + 1) * NUNITS) / NCTA;
    const int gbeg = u0 * 4, gend = u1 * 4;

    const int mo = (wid >> 1) * 32;
    const int no = (wid & 1) * 64;
    const uint32_t arow = (uint32_t)(mo + (lane & 15));
    const uint32_t acol = (uint32_t)(lane >> 4) * 16u;
    const uint32_t brow = (uint32_t)(no + ((lane >> 4) & 1) * 8 + (lane & 7));
    const uint32_t bkof = (uint32_t)((lane >> 3) & 1) * 16u;
    const int tg = lane & 3;

    // ---- prologue: X(rb0) + Y(gbeg) + ysq(gbeg), one commit group ----
    {
        const int rb0 = gbeg >> 6, col = (gbeg & 63) * TN;
        const __half* xg = g_xb + (size_t)rb0 * BM * DD;
        const __half* yg = g_yb + (size_t)col * DD;
        #pragma unroll
        for (int i = 0; i < 8; i++) {
            int c = i * 256 + tid;
            int r = c >> 4, kc = c & 15;
            cp16(xsb[0] + r * YSTRIDE + kc * 16, xg + r * DD + kc * 8);
            cp16(ysb[gbeg & 1] + r * YSTRIDE + kc * 16, yg + r * DD + kc * 8);
        }
        if (tid < 32) cp16(yqb[gbeg & 1] + tid * 16, g_ysq + col + tid * 4);
        asm volatile("cp.async.commit_group;" ::: "memory");
    }

    uint32_t afrag[2][8][4];
    int rb_prev = -1, xb = 0;
    float m_run[4], s_run[4];
    #pragma unroll
    for (int i = 0; i < 4; i++) { m_run[i] = -FLT_MAX; s_run[i] = 0.f; }

    #pragma unroll 1
    for (int g = gbeg; g < gend; g++) {
        const int rb = g >> 6;

        // ---- prefetch g+1 (Y always; X when crossing a row block) ----
        if (g + 1 < gend) {
            const int g2 = g + 1, col2 = (g2 & 63) * TN, rb2 = g2 >> 6;
            const __half* yg = g_yb + (size_t)col2 * DD;
            #pragma unroll
            for (int i = 0; i < 8; i++) {
                int c = i * 256 + tid;
                int r = c >> 4, kc = c & 15;
                cp16(ysb[g2 & 1] + r * YSTRIDE + kc * 16, yg + r * DD + kc * 8);
            }
            if (tid < 32) cp16(yqb[g2 & 1] + tid * 16, g_ysq + col2 + tid * 4);
            if (rb2 != rb) {
                const __half* xg = g_xb + (size_t)rb2 * BM * DD;
                #pragma unroll
                for (int i = 0; i < 8; i++) {
                    int c = i * 256 + tid;
                    int r = c >> 4, kc = c & 15;
                    cp16(xsb[xb ^ 1] + r * YSTRIDE + kc * 16, xg + r * DD + kc * 8);
                }
            }
            asm volatile("cp.async.commit_group;" ::: "memory");
            asm volatile("cp.async.wait_group 1;" ::: "memory");
        } else {
            asm volatile("cp.async.wait_group 0;" ::: "memory");
        }
        __syncthreads();

        // ---- (re)load A fragments on row-block change ----
        if (rb != rb_prev) {
            if (rb_prev >= 0) xb ^= 1;
            #pragma unroll
            for (int mt = 0; mt < 2; mt++)
                #pragma unroll
                for (int kt = 0; kt < 8; kt++)
                    ldsm4(afrag[mt][kt][0], afrag[mt][kt][1],
                          afrag[mt][kt][2], afrag[mt][kt][3],
                          xsb[xb] + (arow + mt * 16u) * YSTRIDE + kt * 32u + acol);
            rb_prev = rb;
        }

        // ---- GEMM tile (f16 accum) ----
        const uint32_t yb = ysb[g & 1];
        uint32_t acc[2][8][2];
        #pragma unroll
        for (int mt = 0; mt < 2; mt++)
            #pragma unroll
            for (int nt = 0; nt < 8; nt++) { acc[mt][nt][0] = 0u; acc[mt][nt][1] = 0u; }

        #pragma unroll
        for (int kt = 0; kt < 8; kt++) {
            #pragma unroll
            for (int np = 0; np < 4; np++) {
                uint32_t b0, b1, b2, b3;
                ldsm4(b0, b1, b2, b3,
                      yb + (brow + np * 16u) * YSTRIDE + kt * 32u + bkof);
                mma_h(acc[0][2 * np],     afrag[0][kt], b0, b1);
                mma_h(acc[1][2 * np],     afrag[1][kt], b0, b1);
                mma_h(acc[0][2 * np + 1], afrag[0][kt], b2, b3);
                mma_h(acc[1][2 * np + 1], afrag[1][kt], b2, b3);
            }
        }

        // ---- epilogue: online log2-sum-exp2 ----
        const float* ysqp = (const float*)(dsm + 139264 + (g & 1) * 512);
        float2 yq[8];
        #pragma unroll
        for (int nt = 0; nt < 8; nt++)
            yq[nt] = *(const float2*)(ysqp + no + nt * 8 + 2 * tg);

        #pragma unroll
        for (int ri = 0; ri < 4; ri++) {
            const int mt = ri >> 1, hi = ri & 1;
            float2 tv[8];
            float vmax = -FLT_MAX;
            #pragma unroll
            for (int nt = 0; nt < 8; nt++) {
                __half2 h = *reinterpret_cast<__half2*>(&acc[mt][nt][hi]);
                float2 f = __half22float2(h);
                tv[nt].x = f.x - yq[nt].x;
                tv[nt].y = f.y - yq[nt].y;
                vmax = fmaxf(vmax, fmaxf(tv[nt].x, tv[nt].y));
            }
            vmax = fmaxf(vmax, __shfl_xor_sync(0xffffffffu, vmax, 1));
            vmax = fmaxf(vmax, __shfl_xor_sync(0xffffffffu, vmax, 2));
            float mn = fmaxf(m_run[ri], vmax);
            float cs = 0.f;
            #pragma unroll
            for (int nt = 0; nt < 8; nt++)
                cs += ex2(tv[nt].x - mn) + ex2(tv[nt].y - mn);
            cs += __shfl_xor_sync(0xffffffffu, cs, 1);
            cs += __shfl_xor_sync(0xffffffffu, cs, 2);
            s_run[ri] = fmaf(s_run[ri], ex2(m_run[ri] - mn), cs);
            m_run[ri] = mn;
        }

        // ---- unit boundary: merge n-halves, flush (m,s), reset ----
        if ((g & 3) == 3) {
            const int u = g >> 2;
            if ((lane & 3) == 0) {
                const int gq = lane >> 2;
                #pragma unroll
                for (int ri = 0; ri < 4; ri++) {
                    int rowl = mo + gq + (ri & 1) * 8 + (ri >> 1) * 16;
                    mh[wid & 1][rowl] = m_run[ri];
                    sh[wid & 1][rowl] = s_run[ri];
                }
            }
            __syncthreads();
            if (tid < BM) {
                float m0 = mh[0][tid], m1 = mh[1][tid];
                float s0 = sh[0][tid], s1 = sh[1][tid];
                float M = fmaxf(m0, m1);
                float S = fmaf(s0, ex2(m0 - M), s1 * ex2(m1 - M));
                g_m[u * BM + tid] = M;
                g_s[u * BM + tid] = S;
            }
            #pragma unroll
            for (int i = 0; i < 4; i++) { m_run[i] = -FLT_MAX; s_run[i] = 0.f; }
        }
    }
}

// ---------------------------------------------------------------------------
// Finalize stage 1: per-row merge of 16 column-unit partials. 32 blocks.
// ---------------------------------------------------------------------------
__global__ void finalize1_kernel() {
    __shared__ float red[8];
    const int tid = threadIdx.x;                 // 256
    const int row = blockIdx.x * 256 + tid;
    const int rb = row >> 7, rl = row & 127;

    float mm[16];
    float M = -FLT_MAX;
    #pragma unroll
    for (int cc = 0; cc < 16; cc++) {
        mm[cc] = g_m[(rb * 16 + cc) * BM + rl];
        M = fmaxf(M, mm[cc]);
    }
    float S = 0.f;
    #pragma unroll
    for (int cc = 0; cc < 16; cc++)
        S += g_s[(rb * 16 + cc) * BM + rl] * ex2(mm[cc] - M);

    float v = LN2 * (M + lg2(S)) - g_diag[row];
    #pragma unroll
    for (int off = 16; off; off >>= 1)
        v += __shfl_xor_sync(0xffffffffu, v, off);
    if ((tid & 31) == 0) red[tid >> 5] = v;
    __syncthreads();
    if (tid == 0) {
        float t = 0.f;
        #pragma unroll
        for (int k = 0; k < 8; k++) t += red[k];
        g_partial[blockIdx.x] = t;
    }
}

__global__ void finalize2_kernel(float* __restrict__ out) {
    int tid = threadIdx.x;  // 32
    float v = g_partial[tid];
    #pragma unroll
    for (int off = 16; off; off >>= 1)
        v += __shfl_xor_sync(0xffffffffu, v, off);
    if (tid == 0) out[0] = v * (1.0f / (float)KTOT);
}

// ---------------------------------------------------------------------------
extern "C" void kernel_launch(void* const* d_in, const int* in_sizes, int n_in,
                              void* d_out, int out_size) {
    const float* X = (const float*)d_in[0];  // features_nc
    const float* Y = (const float*)d_in[1];  // features_c

    const size_t dsmem = 140288;  // 2*X + 2*Y + 2*ysq
    cudaFuncSetAttribute(infonce_mma_kernel,
                         cudaFuncAttributeMaxDynamicSharedMemorySize, (int)dsmem);

    prep_kernel<<<(KTOT * 32) / 256, 256>>>(X, Y);
    infonce_mma_kernel<<<NCTA, 256, dsmem>>>();
    finalize1_kernel<<<32, 256>>>();
    finalize2_kernel<<<1, 32>>>((float*)d_out);
}